// round 14
// baseline (speedup 1.0000x reference)
#include <cuda_runtime.h>
#include <cuda_bf16.h>
#include <math.h>
#include <stdint.h>

// Problem constants
#define B 32
#define T 2048
#define D 1024
#define U 1024
#define NROWS (B*T)          // 65536
#define TS 16                // context t-splits

#if defined(__CUDA_ARCH_FEAT_SM103_ALL) || defined(__CUDA_ARCH_FEAT_SM100_ALL)
#define HAS_TCGEN05 1
#else
#define HAS_TCGEN05 0
#endif

// tcgen05 GEMM (r7-proven): 128 rows/CTA (512 CTAs), N=256/pass, 4 passes,
// k-chunks of 32, SW64, TMEM ping-pong, 4-stage pipeline, warp-specialized.
// NEW: A fp32->bf16 hi/lo conversion runs as a per-CTA PROLOGUE (own rows ->
// own global granules), overlapping across waves; pipeline itself unchanged.
#define GM 128
#define KCH 32
#define NKC 32               // chunks per pass
#define NPASS 4
#define NCH 128              // total chunks
#define NTHREADS 256

// idesc: dtype=F32(1<<4), atype=BF16(1<<7), btype=BF16(1<<10), N/8<<17, M/16<<24
#define MMA_IDESC ((8u<<24) | (32u<<17) | (1u<<10) | (1u<<7) | (1u<<4))

// SMEM layout (offsets from 1024-aligned base)
#define OF_TM    0u
#define OF_FULL  16u             // 4 mbarriers (A+B arrived, tx=48KB)
#define OF_DONE  48u             // 4 mbarriers (MMA chunk commit)
#define OF_PDONE 80u             // 2 mbarriers (pass MMAs complete)
#define OF_EPI   96u             // 2 mbarriers (epilogue drained, cnt=128)
#define OF_PQ    1024u           // 4 KB pq row
#define OF_VV    5120u           // 4 KB V
#define OF_STG   9216u           // 4 stages x 49152
#define SOF_AHI  0u              // 8 KB
#define SOF_ALO  8192u
#define SOF_BHI  16384u          // 16 KB
#define SOF_BLO  32768u
#define STG_BYTES 49152u
#define STG_TX    49152u
#define SMEM_BYTES (9216 + 4*49152 + 1024)

// fallback (mma.sync) config — unchanged
#define FB_NP   8
#define FB_KC   16
#define FB_STRIDE 72
#define FB_TILE (128*FB_STRIDE)
#define FB_SMEM (4*FB_TILE*2)
#define WPAD (D+8)

// Scratch (device globals; no allocation allowed)
__device__ float g_pq[B*U];
__device__ float g_score[NROWS];
__device__ float g_ctxp[TS*B*D];
// tc: A granules [512 rowblocks][32 kc][8KB SW64 (128r x 32k)]
__device__ __align__(16) __nv_bfloat16 g_Ahi[NROWS*D];   // 128 MB
__device__ __align__(16) __nv_bfloat16 g_Alo[NROWS*D];   // 128 MB
// tc: B granules [4 pass][32 kc][16KB SW64 (256u x 32k)]; fallback: [U][WPAD]
__device__ __align__(16) __nv_bfloat16 g_Bhi[U*WPAD];
__device__ __align__(16) __nv_bfloat16 g_Blo[U*WPAD];

// ---------------------------------------------------------------------------
// Common helpers
// ---------------------------------------------------------------------------
__device__ __forceinline__ uint32_t smem_u32(const void* p) {
    uint32_t a;
    asm("{ .reg .u64 t; cvta.to.shared.u64 t, %1; cvt.u32.u64 %0, t; }" : "=r"(a) : "l"(p));
    return a;
}
__device__ __host__ __forceinline__ uint32_t sw64(uint32_t o) { return o ^ ((o >> 3) & 0x30); }

__device__ __forceinline__ unsigned short bfbits(float v) {
    __nv_bfloat16 b = __float2bfloat16(v);
    return *reinterpret_cast<unsigned short*>(&b);
}
__device__ __forceinline__ float fast_tanh(float x) {
    float ax = fabsf(x);
    float e = __expf(ax + ax);
    float t = 1.0f - __fdividef(2.0f, e + 1.0f);
    return copysignf(t, x);
}

extern __shared__ char dynsmem[];

#if HAS_TCGEN05
__device__ __forceinline__ void tm_alloc(uint32_t smem_dst, uint32_t ncols) {
    asm volatile("tcgen05.alloc.cta_group::1.sync.aligned.shared::cta.b32 [%0], %1;"
                 :: "r"(smem_dst), "r"(ncols) : "memory");
}
__device__ __forceinline__ void tm_relinquish() {
    asm volatile("tcgen05.relinquish_alloc_permit.cta_group::1.sync.aligned;");
}
__device__ __forceinline__ void tm_dealloc(uint32_t tmem, uint32_t ncols) {
    asm volatile("tcgen05.dealloc.cta_group::1.sync.aligned.b32 %0, %1;" :: "r"(tmem), "r"(ncols));
}
__device__ __forceinline__ void mma_f16_ss(uint32_t d_tmem, uint64_t a_desc, uint64_t b_desc,
                                           uint32_t idesc, uint32_t en) {
    asm volatile("{\n\t.reg .pred p;\n\t"
                 "setp.ne.u32 p, %5, 0;\n\t"
                 "tcgen05.mma.cta_group::1.kind::f16 [%0], %1, %2, %3, {%4, %4, %4, %4}, p;\n\t}"
                 :: "r"(d_tmem), "l"(a_desc), "l"(b_desc), "r"(idesc), "r"(0u), "r"(en)
                 : "memory");
}
__device__ __forceinline__ void tm_commit(uint32_t mbar) {
    asm volatile("tcgen05.commit.cta_group::1.mbarrier::arrive::one.shared::cluster.b64 [%0];"
                 :: "r"(mbar) : "memory");
}
__device__ __forceinline__ void tc_fence_after() {
    asm volatile("tcgen05.fence::after_thread_sync;" ::: "memory");
}
__device__ __forceinline__ void tc_fence_before() {
    asm volatile("tcgen05.fence::before_thread_sync;" ::: "memory");
}
__device__ __forceinline__ void tc_wait_ld() {
    asm volatile("tcgen05.wait::ld.sync.aligned;" ::: "memory");
}
#define TCLD32(r, a) \
    asm volatile("tcgen05.ld.sync.aligned.32x32b.x32.b32 " \
        "{%0, %1, %2, %3, %4, %5, %6, %7, %8, %9, %10, %11, %12, %13, %14, %15, " \
        " %16, %17, %18, %19, %20, %21, %22, %23, %24, %25, %26, %27, %28, %29, %30, %31}, [%32];" \
        : "=r"((r)[0]),  "=r"((r)[1]),  "=r"((r)[2]),  "=r"((r)[3]), \
          "=r"((r)[4]),  "=r"((r)[5]),  "=r"((r)[6]),  "=r"((r)[7]), \
          "=r"((r)[8]),  "=r"((r)[9]),  "=r"((r)[10]), "=r"((r)[11]), \
          "=r"((r)[12]), "=r"((r)[13]), "=r"((r)[14]), "=r"((r)[15]), \
          "=r"((r)[16]), "=r"((r)[17]), "=r"((r)[18]), "=r"((r)[19]), \
          "=r"((r)[20]), "=r"((r)[21]), "=r"((r)[22]), "=r"((r)[23]), \
          "=r"((r)[24]), "=r"((r)[25]), "=r"((r)[26]), "=r"((r)[27]), \
          "=r"((r)[28]), "=r"((r)[29]), "=r"((r)[30]), "=r"((r)[31]) \
        : "r"(a))
// SW64 descriptor: layout_type=4, version=1, SBO=32 (512B = 8 rows x 64B), LBO=1
__device__ __forceinline__ uint64_t make_desc64(uint32_t addr) {
    const uint64_t base = (uint64_t(4) << 61) | (uint64_t(1) << 46) |
                          (uint64_t(32) << 32) | (uint64_t(1) << 16);
    return base | ((uint64_t)(addr >> 4) & 0x3FFF);
}
__device__ __forceinline__ void bulk_g2s(uint32_t dst, const void* src, uint32_t bytes, uint32_t mbar) {
    asm volatile("cp.async.bulk.shared::cluster.global.mbarrier::complete_tx::bytes [%0], [%1], %2, [%3];"
                 :: "r"(dst), "l"(src), "r"(bytes), "r"(mbar) : "memory");
}
__device__ __forceinline__ void mbar_expect_tx(uint32_t a, uint32_t bytes) {
    asm volatile("mbarrier.arrive.expect_tx.shared.b64 _, [%0], %1;" :: "r"(a), "r"(bytes) : "memory");
}
#endif  // HAS_TCGEN05

__device__ __forceinline__ void mbar_init(uint32_t a, uint32_t cnt) {
    asm volatile("mbarrier.init.shared.b64 [%0], %1;" :: "r"(a), "r"(cnt) : "memory");
}
__device__ __forceinline__ void mbar_inval(uint32_t a) {
    asm volatile("mbarrier.inval.shared.b64 [%0];" :: "r"(a) : "memory");
}
__device__ __forceinline__ void mbar_arrive(uint32_t a) {
    asm volatile("mbarrier.arrive.shared.b64 _, [%0];" :: "r"(a) : "memory");
}
__device__ __forceinline__ void mbar_wait(uint32_t a, uint32_t parity) {
    uint32_t done;
    asm volatile("{\n\t.reg .pred p;\n\t"
                 "mbarrier.try_wait.parity.acquire.cta.shared::cta.b64 p, [%1], %2;\n\t"
                 "selp.b32 %0, 1, 0, p;\n\t}"
                 : "=r"(done) : "r"(a), "r"(parity) : "memory");
    if (!done) {
        asm volatile("{\n\t.reg .pred P1;\n\t"
                     "WL_%=:\n\t"
                     "mbarrier.try_wait.parity.acquire.cta.shared::cta.b64 P1, [%0], %1, 0x989680;\n\t"
                     "@P1 bra.uni WD_%=;\n\t"
                     "bra.uni WL_%=;\n\t"
                     "WD_%=:\n\t}"
                     :: "r"(a), "r"(parity) : "memory");
    }
}

// ---------------------------------------------------------------------------
// Fallback (mma.sync) helpers — legal on plain compute_103
// ---------------------------------------------------------------------------
__device__ __forceinline__ void ldsm_x4(uint32_t& r0, uint32_t& r1, uint32_t& r2, uint32_t& r3,
                                        uint32_t addr) {
    asm volatile("ldmatrix.sync.aligned.m8n8.x4.shared.b16 {%0,%1,%2,%3}, [%4];"
                 : "=r"(r0), "=r"(r1), "=r"(r2), "=r"(r3) : "r"(addr));
}
__device__ __forceinline__ void mma16816(float* d, const uint32_t* a, uint32_t b0, uint32_t b1) {
    asm volatile("mma.sync.aligned.m16n8k16.row.col.f32.bf16.bf16.f32 "
                 "{%0,%1,%2,%3}, {%4,%5,%6,%7}, {%8,%9}, {%0,%1,%2,%3};"
                 : "+f"(d[0]), "+f"(d[1]), "+f"(d[2]), "+f"(d[3])
                 : "r"(a[0]), "r"(a[1]), "r"(a[2]), "r"(a[3]), "r"(b0), "r"(b1));
}

// ---------------------------------------------------------------------------
// Kernel 1 (prep): blocks [0,128) = W1 convert; [128,160) = pq.
// (A conversion moved into the GEMM prologue.)
// ---------------------------------------------------------------------------
__global__ void __launch_bounds__(256)
prep_kernel(const float* __restrict__ W1,
            const float* __restrict__ query, const float* __restrict__ W2,
            const float* __restrict__ b1, const float* __restrict__ b2) {
    const int blk = blockIdx.x;
    const int tid = threadIdx.x;
    __shared__ float q[D];

    if (blk < 128) {
        const int g2 = blk;                  // 0..127 = pass*32 + kc
#if HAS_TCGEN05
        const int pass = g2 >> 5;
        const int kc = g2 & 31;
        char* dhi = (char*)g_Bhi + (size_t)g2 * 16384;
        char* dlo = (char*)g_Blo + (size_t)g2 * 16384;
        const int k0 = kc*KCH, u0 = pass*256;
        const int ul = tid;
        for (int k4 = 0; k4 < 8; k4++) {
            float f[4];
            #pragma unroll
            for (int j = 0; j < 4; j++) f[j] = W1[(size_t)(k0 + k4*4 + j)*U + u0 + ul];
            unsigned short h[4], l[4];
            #pragma unroll
            for (int j = 0; j < 4; j++) {
                h[j] = bfbits(f[j]);
                __nv_bfloat16 hb = *reinterpret_cast<__nv_bfloat16*>(&h[j]);
                l[j] = bfbits(f[j] - __bfloat162float(hb));
            }
            uint32_t off = sw64((uint32_t)ul*64 + k4*8);
            *(uint2*)(dhi + off) = make_uint2((uint32_t)h[0] | ((uint32_t)h[1] << 16),
                                              (uint32_t)h[2] | ((uint32_t)h[3] << 16));
            *(uint2*)(dlo + off) = make_uint2((uint32_t)l[0] | ((uint32_t)l[1] << 16),
                                              (uint32_t)l[2] | ((uint32_t)l[3] << 16));
        }
#else
        const int k0 = (g2 & 31)*32;
        const int u  = (g2 >> 5)*256 + tid;
        for (int k4 = 0; k4 < 8; k4++) {
            float f[4];
            #pragma unroll
            for (int j = 0; j < 4; j++) f[j] = W1[(size_t)(k0 + k4*4 + j)*U + u];
            unsigned short h[4], l[4];
            #pragma unroll
            for (int j = 0; j < 4; j++) {
                h[j] = bfbits(f[j]);
                __nv_bfloat16 hb = *reinterpret_cast<__nv_bfloat16*>(&h[j]);
                l[j] = bfbits(f[j] - __bfloat162float(hb));
            }
            *(uint2*)&g_Bhi[(size_t)u*WPAD + k0 + k4*4] =
                make_uint2((uint32_t)h[0] | ((uint32_t)h[1] << 16),
                           (uint32_t)h[2] | ((uint32_t)h[3] << 16));
            *(uint2*)&g_Blo[(size_t)u*WPAD + k0 + k4*4] =
                make_uint2((uint32_t)l[0] | ((uint32_t)l[1] << 16),
                           (uint32_t)l[2] | ((uint32_t)l[3] << 16));
        }
#endif
    } else {
        const int b = blk - 128;
        for (int i = tid; i < D; i += 256) q[i] = query[b*D + i];
        __syncthreads();
        int u = tid;
        float a0 = 0.f, a1 = 0.f, a2 = 0.f, a3 = 0.f;
        for (int d = 0; d < D; d++) {
            float qd = q[d];
            const float* w = &W2[(size_t)d*U + u];
            a0 += qd * w[0];   a1 += qd * w[256];
            a2 += qd * w[512]; a3 += qd * w[768];
        }
        g_pq[b*U + u      ] = a0 + b1[u      ] + b2[u      ];
        g_pq[b*U + u + 256] = a1 + b1[u + 256] + b2[u + 256];
        g_pq[b*U + u + 512] = a2 + b1[u + 512] + b2[u + 512];
        g_pq[b*U + u + 768] = a3 + b1[u + 768] + b2[u + 768];
    }
}

// ---------------------------------------------------------------------------
// Kernel 2a: tcgen05 score GEMM — r7 pipeline + per-CTA A-convert PROLOGUE.
// ---------------------------------------------------------------------------
#if HAS_TCGEN05
__device__ __forceinline__ void issue_copies(uint32_t sb, int rb, int g) {
    const int slot = g & 3;
    const uint32_t st = sb + OF_STG + slot*STG_BYTES;
    const uint32_t full = sb + OF_FULL + 8*slot;
    mbar_expect_tx(full, STG_TX);
    size_t aoff = ((size_t)rb*32 + (g & 31)) * 8192;
    size_t boff = (size_t)g * 16384;
    bulk_g2s(st + SOF_AHI, (const char*)g_Ahi + aoff,  8192, full);
    bulk_g2s(st + SOF_ALO, (const char*)g_Alo + aoff,  8192, full);
    bulk_g2s(st + SOF_BHI, (const char*)g_Bhi + boff, 16384, full);
    bulk_g2s(st + SOF_BLO, (const char*)g_Blo + boff, 16384, full);
}
#endif

__global__ void __launch_bounds__(NTHREADS, 1)
score_gemm_tc(const float* __restrict__ values, const float* __restrict__ Vv) {
#if HAS_TCGEN05
    const uint32_t raw = smem_u32(dynsmem);
    const uint32_t sb = (raw + 1023) & ~1023u;
    char* sbp = dynsmem + (sb - raw);

    const int tid = threadIdx.x;
    const int wid = tid >> 5;
    const int lane = tid & 31;
    const int rb  = blockIdx.x;
    const int row0 = rb * GM;
    const int bidx = row0 / T;

    if (wid == 0) {
        tm_alloc(sb + OF_TM, 512);
        tm_relinquish();
    }
    if (tid == 0) {
        #pragma unroll
        for (int s = 0; s < 4; s++) {
            mbar_init(sb + OF_FULL + 8*s, 1);
            mbar_init(sb + OF_DONE + 8*s, 1);
        }
        mbar_init(sb + OF_PDONE,     1);
        mbar_init(sb + OF_PDONE + 8, 1);
        mbar_init(sb + OF_EPI,     128);
        mbar_init(sb + OF_EPI + 8, 128);
    }
    {
        ((float4*)(sbp + OF_PQ))[tid] = ((const float4*)(g_pq + bidx*U))[tid];
        ((float4*)(sbp + OF_VV))[tid] = ((const float4*)Vv)[tid];
    }

    // ---------------- PROLOGUE: convert own 128 rows to bf16 hi/lo granules --
    {
        const float4* src = reinterpret_cast<const float4*>(values) + (size_t)row0*256;
        for (int kc = 0; kc < 32; kc++) {
            char* dhi = (char*)g_Ahi + ((size_t)rb*32 + kc) * 8192;
            char* dlo = (char*)g_Alo + ((size_t)rb*32 + kc) * 8192;
            #pragma unroll
            for (int i = 0; i < 4; i++) {
                int idx = tid + 256*i;       // 0..1023
                int r = idx >> 3;            // 0..127
                int s = idx & 7;
                float4 v = src[(size_t)r*256 + kc*8 + s];
                float f[4] = {v.x, v.y, v.z, v.w};
                unsigned short h[4], l[4];
                #pragma unroll
                for (int j = 0; j < 4; j++) {
                    h[j] = bfbits(f[j]);
                    __nv_bfloat16 hb = *reinterpret_cast<__nv_bfloat16*>(&h[j]);
                    l[j] = bfbits(f[j] - __bfloat162float(hb));
                }
                uint32_t off = sw64((uint32_t)r*64 + s*8);
                *(uint2*)(dhi + off) = make_uint2((uint32_t)h[0] | ((uint32_t)h[1] << 16),
                                                  (uint32_t)h[2] | ((uint32_t)h[3] << 16));
                *(uint2*)(dlo + off) = make_uint2((uint32_t)l[0] | ((uint32_t)l[1] << 16),
                                                  (uint32_t)l[2] | ((uint32_t)l[3] << 16));
            }
        }
        __threadfence();     // make our STGs visible GPU-wide (L2) ...
        __syncthreads();     // ... and establish happens-before for tid0
        asm volatile("fence.proxy.async;" ::: "memory");  // generic -> async proxy
    }

    const uint32_t tmem = *(volatile uint32_t*)(sbp + OF_TM);

    if (tid == 0) {
        tc_fence_after();
        issue_copies(sb, rb, 0);
        issue_copies(sb, rb, 1);
        issue_copies(sb, rb, 2);
        issue_copies(sb, rb, 3);
        for (int p = 0; p < NPASS; p++) {
            if (p >= 2) {
                mbar_wait(sb + OF_EPI + 8*(p & 1), 0);
                tc_fence_after();
            }
            const uint32_t dt = tmem + (p & 1)*256;
            for (int c = 0; c < NKC; c++) {
                const int g = p*NKC + c;
                const int slot = g & 3;
                mbar_wait(sb + OF_FULL + 8*slot, (uint32_t)((g >> 2) & 1));
                const uint32_t st = sb + OF_STG + slot*STG_BYTES;
                uint64_t adh = make_desc64(st + SOF_AHI);
                uint64_t adl = make_desc64(st + SOF_ALO);
                uint64_t bdh = make_desc64(st + SOF_BHI);
                uint64_t bdl = make_desc64(st + SOF_BLO);
                #pragma unroll
                for (int ks = 0; ks < 2; ks++) {
                    uint64_t o = (uint64_t)(ks*2);
                    uint32_t en0 = (c > 0 || ks > 0) ? 1u : 0u;
                    mma_f16_ss(dt, adh + o, bdh + o, MMA_IDESC, en0);
                    mma_f16_ss(dt, adh + o, bdl + o, MMA_IDESC, 1u);
                    mma_f16_ss(dt, adl + o, bdh + o, MMA_IDESC, 1u);
                }
                tm_commit(sb + OF_DONE + 8*slot);
                if (g >= 1 && g + 3 < NCH) {
                    const int gp = g - 1;
                    mbar_wait(sb + OF_DONE + 8*(gp & 3), (uint32_t)((gp >> 2) & 1));
                    issue_copies(sb, rb, g + 3);
                }
            }
            tm_commit(sb + OF_PDONE + 8*(p & 1));
        }
    } else if (wid >= 4) {
        float score = 0.f;
        const int myrow = (wid - 4)*32 + lane;
        const float* pqs = (const float*)(sbp + OF_PQ);
        const float* vvs = (const float*)(sbp + OF_VV);
        for (int p = 0; p < NPASS; p++) {
            mbar_wait(sb + OF_PDONE + 8*(p & 1), (uint32_t)((p >> 1) & 1));
            tc_fence_after();
            const uint32_t dbase = tmem + (p & 1)*256;
            #pragma unroll
            for (int j = 0; j < 8; j++) {
                uint32_t r[32];
                TCLD32(r, dbase + j*32);
                tc_wait_ld();
                #pragma unroll
                for (int c2 = 0; c2 < 32; c2++) {
                    int u = p*256 + j*32 + c2;
                    float dv = __uint_as_float(r[c2]);
                    score += fast_tanh(dv + pqs[u]) * vvs[u];
                }
            }
            tc_fence_before();
            mbar_arrive(sb + OF_EPI + 8*(p & 1));
        }
        g_score[row0 + myrow] = score;
    }
    __syncthreads();
    if (tid == 0) {
        #pragma unroll
        for (int s = 0; s < 4; s++) {
            mbar_inval(sb + OF_FULL + 8*s);
            mbar_inval(sb + OF_DONE + 8*s);
        }
        mbar_inval(sb + OF_PDONE); mbar_inval(sb + OF_PDONE + 8);
        mbar_inval(sb + OF_EPI);   mbar_inval(sb + OF_EPI + 8);
    }
    __syncthreads();
    if (wid == 0) tm_dealloc(tmem, 512);
#endif  // HAS_TCGEN05
}

// ---------------------------------------------------------------------------
// Kernel 2b: fallback mma.sync (HMMA) score GEMM (body only on plain sm_103)
// ---------------------------------------------------------------------------
__global__ void __launch_bounds__(256)
score_gemm_mma(const float* __restrict__ values, const float* __restrict__ Vv) {
#if !HAS_TCGEN05
    const int tid  = threadIdx.x;
    const int wid  = tid >> 5;
    const int lane = tid & 31;
    const int row0 = blockIdx.x * 128;
    const int bidx = row0 / T;
    const int c = lane & 3;
    const int g = lane >> 2;

    __nv_bfloat16* As_hi = (__nv_bfloat16*)dynsmem;
    __nv_bfloat16* As_lo = As_hi + FB_TILE;
    __nv_bfloat16* Bs_hi = As_lo + FB_TILE;
    __nv_bfloat16* Bs_lo = Bs_hi + FB_TILE;
    const uint32_t smb   = smem_u32(dynsmem);
    const uint32_t ahi_b = smb;
    const uint32_t alo_b = smb + FB_TILE*2;
    const uint32_t bhi_b = smb + 2*FB_TILE*2;
    const uint32_t blo_b = smb + 3*FB_TILE*2;

    float score0 = 0.f, score1 = 0.f;

    for (int p = 0; p < FB_NP; p++) {
        const int u0 = p * 128;
        float acc[16][4];
        #pragma unroll
        for (int i = 0; i < 16; i++)
            #pragma unroll
            for (int j = 0; j < 4; j++) acc[i][j] = 0.f;

        for (int kc = 0; kc < FB_KC; kc++) {
            const int k0 = kc * 64;
            #pragma unroll
            for (int i = 0; i < 8; i++) {
                int idx = tid + 256*i;
                int r = idx >> 4;
                int s = idx & 15;
                float4 v = *(const float4*)&values[(size_t)(row0 + r)*D + k0 + s*4];
                float f[4] = {v.x, v.y, v.z, v.w};
                unsigned short h[4], l[4];
                #pragma unroll
                for (int j = 0; j < 4; j++) {
                    h[j] = bfbits(f[j]);
                    __nv_bfloat16 hb = *reinterpret_cast<__nv_bfloat16*>(&h[j]);
                    l[j] = bfbits(f[j] - __bfloat162float(hb));
                }
                *(uint2*)&As_hi[r*FB_STRIDE + s*4] =
                    make_uint2((uint32_t)h[0] | ((uint32_t)h[1] << 16),
                               (uint32_t)h[2] | ((uint32_t)h[3] << 16));
                *(uint2*)&As_lo[r*FB_STRIDE + s*4] =
                    make_uint2((uint32_t)l[0] | ((uint32_t)l[1] << 16),
                               (uint32_t)l[2] | ((uint32_t)l[3] << 16));
            }
            #pragma unroll
            for (int i = 0; i < 4; i++) {
                int idx = tid + 256*i;
                int n = idx >> 3;
                int m = idx & 7;
                *(uint4*)&Bs_hi[n*FB_STRIDE + m*8] =
                    *(const uint4*)&g_Bhi[(size_t)(u0 + n)*WPAD + k0 + m*8];
                *(uint4*)&Bs_lo[n*FB_STRIDE + m*8] =
                    *(const uint4*)&g_Blo[(size_t)(u0 + n)*WPAD + k0 + m*8];
            }
            __syncthreads();

            #pragma unroll
            for (int ks = 0; ks < 4; ks++) {
                uint32_t ah[4], al[4];
                uint32_t aoff = ((uint32_t)(16*wid + (lane & 15))*FB_STRIDE
                                 + ks*16 + ((lane >> 4) << 3)) * 2;
                ldsm_x4(ah[0], ah[1], ah[2], ah[3], ahi_b + aoff);
                ldsm_x4(al[0], al[1], al[2], al[3], alo_b + aoff);

                #pragma unroll
                for (int nt2 = 0; nt2 < 8; nt2++) {
                    int mtx = lane >> 3, r8 = lane & 7;
                    uint32_t n   = nt2*16 + ((mtx >> 1) << 3) + r8;
                    uint32_t kof = ks*16 + ((mtx & 1) << 3);
                    uint32_t boff = (n*FB_STRIDE + kof) * 2;
                    uint32_t bh0, bh1, bh2, bh3, bl0, bl1, bl2, bl3;
                    ldsm_x4(bh0, bh1, bh2, bh3, bhi_b + boff);
                    ldsm_x4(bl0, bl1, bl2, bl3, blo_b + boff);
                    mma16816(acc[2*nt2],     ah, bh0, bh1);
                    mma16816(acc[2*nt2],     ah, bl0, bl1);
                    mma16816(acc[2*nt2],     al, bh0, bh1);
                    mma16816(acc[2*nt2 + 1], ah, bh2, bh3);
                    mma16816(acc[2*nt2 + 1], ah, bl2, bl3);
                    mma16816(acc[2*nt2 + 1], al, bh2, bh3);
                }
            }
            __syncthreads();
        }

        #pragma unroll
        for (int nt = 0; nt < 16; nt++) {
            #pragma unroll
            for (int j = 0; j < 2; j++) {
                int u = u0 + nt*8 + 2*c + j;
                float pqv = g_pq[bidx*U + u];
                float vv  = Vv[u];
                score0 += tanhf(acc[nt][j]     + pqv) * vv;
                score1 += tanhf(acc[nt][2 + j] + pqv) * vv;
            }
        }
    }

    score0 += __shfl_xor_sync(0xffffffffu, score0, 1);
    score0 += __shfl_xor_sync(0xffffffffu, score0, 2);
    score1 += __shfl_xor_sync(0xffffffffu, score1, 1);
    score1 += __shfl_xor_sync(0xffffffffu, score1, 2);
    if (c == 0) {
        g_score[row0 + wid*16 + g]     = score0;
        g_score[row0 + wid*16 + 8 + g] = score1;
    }
#endif  // !HAS_TCGEN05
}

// ---------------------------------------------------------------------------
// Kernel 3: mask + softmax over T -> attention weights (r7-proven)
// ---------------------------------------------------------------------------
__global__ void softmax_kernel(const float* __restrict__ mask,
                               const float* __restrict__ bV,
                               float* __restrict__ attn) {
    const int b = blockIdx.x;
    __shared__ float sc[T];
    __shared__ float redbuf[256];
    const float bv = bV[0];

    for (int t = threadIdx.x; t < T; t += 256)
        sc[t] = g_score[b*T + t] + bv + mask[b*T + t] * (-1e9f);
    __syncthreads();

    float m = -INFINITY;
    for (int t = threadIdx.x; t < T; t += 256) m = fmaxf(m, sc[t]);
    redbuf[threadIdx.x] = m;
    __syncthreads();
    for (int s = 128; s > 0; s >>= 1) {
        if (threadIdx.x < s) redbuf[threadIdx.x] = fmaxf(redbuf[threadIdx.x], redbuf[threadIdx.x + s]);
        __syncthreads();
    }
    m = redbuf[0];
    __syncthreads();

    float sum = 0.f;
    for (int t = threadIdx.x; t < T; t += 256) {
        float e = expf(sc[t] - m);
        sc[t] = e;
        sum += e;
    }
    redbuf[threadIdx.x] = sum;
    __syncthreads();
    for (int s = 128; s > 0; s >>= 1) {
        if (threadIdx.x < s) redbuf[threadIdx.x] += redbuf[threadIdx.x + s];
        __syncthreads();
    }
    const float inv = 1.f / redbuf[0];
    __syncthreads();

    for (int t = threadIdx.x; t < T; t += 256) attn[b*T + t] = sc[t] * inv;
}

// ---------------------------------------------------------------------------
// Kernel 4/5: context = sum_t attn * values (r7-proven, TS=16)
// ---------------------------------------------------------------------------
__global__ void __launch_bounds__(256)
context_partial_kernel(const float* __restrict__ values,
                       const float* __restrict__ attn) {
    const int ts = blockIdx.x;
    const int b  = blockIdx.y;
    const int t0 = ts * (T / TS);
    const int tid = threadIdx.x;

    __shared__ float w[T / TS];
    if (tid < T / TS) w[tid] = attn[b*T + t0 + tid];
    __syncthreads();

    const float4* vp = (const float4*)(values + ((size_t)b*T + t0) * D) + tid;
    float4 acc = make_float4(0.f, 0.f, 0.f, 0.f);
    #pragma unroll 4
    for (int t = 0; t < T / TS; t++) {
        float4 v = vp[(size_t)t * (D/4)];
        float wt = w[t];
        acc.x += wt * v.x; acc.y += wt * v.y;
        acc.z += wt * v.z; acc.w += wt * v.w;
    }
    ((float4*)(g_ctxp + ((size_t)ts*B + b) * D))[tid] = acc;
}

__global__ void context_reduce_kernel(float* __restrict__ ctx) {
    int i = blockIdx.x * 256 + threadIdx.x;
    float s = 0.f;
    #pragma unroll
    for (int p = 0; p < TS; p++) s += g_ctxp[(size_t)p*B*D + i];
    ctx[i] = s;
}

// ---------------------------------------------------------------------------
extern "C" void kernel_launch(void* const* d_in, const int* in_sizes, int n_in,
                              void* d_out, int out_size) {
    const float* values = (const float*)d_in[0];
    const float* query  = (const float*)d_in[1];
    const float* mask   = (const float*)d_in[2];
    const float* W1     = (const float*)d_in[3];
    const float* b1     = (const float*)d_in[4];
    const float* W2     = (const float*)d_in[5];
    const float* b2     = (const float*)d_in[6];
    const float* Vv     = (const float*)d_in[7];
    const float* bV     = (const float*)d_in[8];

    float* ctx  = (float*)d_out;
    float* attn = (float*)d_out + B*D;

    cudaFuncSetAttribute(score_gemm_tc,  cudaFuncAttributeMaxDynamicSharedMemorySize, SMEM_BYTES);
    cudaFuncSetAttribute(score_gemm_mma, cudaFuncAttributeMaxDynamicSharedMemorySize, FB_SMEM);

    prep_kernel<<<160, 256>>>(W1, query, W2, b1, b2);

    // Exactly one of these has a body (compile-time arch feature selection).
    score_gemm_tc <<<NROWS/GM, NTHREADS, SMEM_BYTES>>>(values, Vv);
    score_gemm_mma<<<NROWS/128, 256, FB_SMEM>>>(values, Vv);

    softmax_kernel<<<B, 256>>>(mask, bV, attn);
    dim3 cgrid(TS, B);
    context_partial_kernel<<<cgrid, 256>>>(values, attn);
    context_reduce_kernel<<<(B*D)/256, 256>>>(ctx);
}

// round 15
// speedup vs baseline: 1.1110x; 1.1110x over previous
#include <cuda_runtime.h>
#include <cuda_bf16.h>
#include <math.h>
#include <stdint.h>

// Problem constants
#define B 32
#define T 2048
#define D 1024
#define U 1024
#define NROWS (B*T)          // 65536
#define TS 16                // context t-splits

#if defined(__CUDA_ARCH_FEAT_SM103_ALL) || defined(__CUDA_ARCH_FEAT_SM100_ALL)
#define HAS_TCGEN05 1
#else
#define HAS_TCGEN05 0
#endif

// tcgen05 GEMM (r7-proven, 586us): 128 rows/CTA (512 CTAs), N=256/pass,
// 4 passes, k-chunks of 32, SW64, TMEM ping-pong (pass p -> cols (p&1)*256),
// 4-stage cp.async.bulk pipeline, warp-specialized (tid0 driver, w4-7 epilogue).
#define GM 128
#define KCH 32
#define NKC 32               // chunks per pass
#define NPASS 4
#define NCH 128              // total chunks
#define NTHREADS 256

// idesc: dtype=F32(1<<4), atype=BF16(1<<7), btype=BF16(1<<10), N/8<<17, M/16<<24
#define MMA_IDESC ((8u<<24) | (32u<<17) | (1u<<10) | (1u<<7) | (1u<<4))

// SMEM layout (offsets from 1024-aligned base)
#define OF_TM    0u
#define OF_FULL  16u             // 4 mbarriers (A+B arrived, tx=48KB)
#define OF_DONE  48u             // 4 mbarriers (MMA chunk commit)
#define OF_PDONE 80u             // 2 mbarriers (pass MMAs complete)
#define OF_EPI   96u             // 2 mbarriers (epilogue drained, cnt=128)
#define OF_PQ    1024u           // 4 KB pq row
#define OF_VV    5120u           // 4 KB V
#define OF_STG   9216u           // 4 stages x 49152
#define SOF_AHI  0u              // 8 KB
#define SOF_ALO  8192u
#define SOF_BHI  16384u          // 16 KB
#define SOF_BLO  32768u
#define STG_BYTES 49152u
#define STG_TX    49152u
#define SMEM_BYTES (9216 + 4*49152 + 1024)

// fallback (mma.sync) config — unchanged
#define FB_NP   8
#define FB_KC   16
#define FB_STRIDE 72
#define FB_TILE (128*FB_STRIDE)
#define FB_SMEM (4*FB_TILE*2)
#define WPAD (D+8)

// Scratch (device globals; no allocation allowed)
__device__ float g_pq[B*U];
__device__ float g_score[NROWS];
__device__ float g_ctxp[TS*B*D];
// tc: A granules [512 rowblocks][32 kc][8KB SW64 (128r x 32k)]
__device__ __align__(16) __nv_bfloat16 g_Ahi[NROWS*D];   // 128 MB
__device__ __align__(16) __nv_bfloat16 g_Alo[NROWS*D];   // 128 MB
// tc: B granules [4 pass][32 kc][16KB SW64 (256u x 32k)]; fallback: [U][WPAD]
__device__ __align__(16) __nv_bfloat16 g_Bhi[U*WPAD];
__device__ __align__(16) __nv_bfloat16 g_Blo[U*WPAD];

// ---------------------------------------------------------------------------
// Common helpers
// ---------------------------------------------------------------------------
__device__ __forceinline__ uint32_t smem_u32(const void* p) {
    uint32_t a;
    asm("{ .reg .u64 t; cvta.to.shared.u64 t, %1; cvt.u32.u64 %0, t; }" : "=r"(a) : "l"(p));
    return a;
}
__device__ __host__ __forceinline__ uint32_t sw64(uint32_t o) { return o ^ ((o >> 3) & 0x30); }

__device__ __forceinline__ unsigned short bfbits(float v) {
    __nv_bfloat16 b = __float2bfloat16(v);
    return *reinterpret_cast<unsigned short*>(&b);
}
__device__ __forceinline__ float fast_tanh(float x) {
    float ax = fabsf(x);
    float e = __expf(ax + ax);
    float t = 1.0f - __fdividef(2.0f, e + 1.0f);
    return copysignf(t, x);
}
// pack 4 floats -> (hi bf16 x4, lo bf16 x4) as two uint2
__device__ __forceinline__ void split4(const float* f, uint2& hp, uint2& lp) {
    unsigned short h[4], l[4];
    #pragma unroll
    for (int j = 0; j < 4; j++) {
        h[j] = bfbits(f[j]);
        __nv_bfloat16 hb = *reinterpret_cast<__nv_bfloat16*>(&h[j]);
        l[j] = bfbits(f[j] - __bfloat162float(hb));
    }
    hp = make_uint2((uint32_t)h[0] | ((uint32_t)h[1] << 16),
                    (uint32_t)h[2] | ((uint32_t)h[3] << 16));
    lp = make_uint2((uint32_t)l[0] | ((uint32_t)l[1] << 16),
                    (uint32_t)l[2] | ((uint32_t)l[3] << 16));
}

extern __shared__ char dynsmem[];

#if HAS_TCGEN05
__device__ __forceinline__ void tm_alloc(uint32_t smem_dst, uint32_t ncols) {
    asm volatile("tcgen05.alloc.cta_group::1.sync.aligned.shared::cta.b32 [%0], %1;"
                 :: "r"(smem_dst), "r"(ncols) : "memory");
}
__device__ __forceinline__ void tm_relinquish() {
    asm volatile("tcgen05.relinquish_alloc_permit.cta_group::1.sync.aligned;");
}
__device__ __forceinline__ void tm_dealloc(uint32_t tmem, uint32_t ncols) {
    asm volatile("tcgen05.dealloc.cta_group::1.sync.aligned.b32 %0, %1;" :: "r"(tmem), "r"(ncols));
}
__device__ __forceinline__ void mma_f16_ss(uint32_t d_tmem, uint64_t a_desc, uint64_t b_desc,
                                           uint32_t idesc, uint32_t en) {
    asm volatile("{\n\t.reg .pred p;\n\t"
                 "setp.ne.u32 p, %5, 0;\n\t"
                 "tcgen05.mma.cta_group::1.kind::f16 [%0], %1, %2, %3, {%4, %4, %4, %4}, p;\n\t}"
                 :: "r"(d_tmem), "l"(a_desc), "l"(b_desc), "r"(idesc), "r"(0u), "r"(en)
                 : "memory");
}
__device__ __forceinline__ void tm_commit(uint32_t mbar) {
    asm volatile("tcgen05.commit.cta_group::1.mbarrier::arrive::one.shared::cluster.b64 [%0];"
                 :: "r"(mbar) : "memory");
}
__device__ __forceinline__ void tc_fence_after() {
    asm volatile("tcgen05.fence::after_thread_sync;" ::: "memory");
}
__device__ __forceinline__ void tc_fence_before() {
    asm volatile("tcgen05.fence::before_thread_sync;" ::: "memory");
}
__device__ __forceinline__ void tc_wait_ld() {
    asm volatile("tcgen05.wait::ld.sync.aligned;" ::: "memory");
}
#define TCLD32(r, a) \
    asm volatile("tcgen05.ld.sync.aligned.32x32b.x32.b32 " \
        "{%0, %1, %2, %3, %4, %5, %6, %7, %8, %9, %10, %11, %12, %13, %14, %15, " \
        " %16, %17, %18, %19, %20, %21, %22, %23, %24, %25, %26, %27, %28, %29, %30, %31}, [%32];" \
        : "=r"((r)[0]),  "=r"((r)[1]),  "=r"((r)[2]),  "=r"((r)[3]), \
          "=r"((r)[4]),  "=r"((r)[5]),  "=r"((r)[6]),  "=r"((r)[7]), \
          "=r"((r)[8]),  "=r"((r)[9]),  "=r"((r)[10]), "=r"((r)[11]), \
          "=r"((r)[12]), "=r"((r)[13]), "=r"((r)[14]), "=r"((r)[15]), \
          "=r"((r)[16]), "=r"((r)[17]), "=r"((r)[18]), "=r"((r)[19]), \
          "=r"((r)[20]), "=r"((r)[21]), "=r"((r)[22]), "=r"((r)[23]), \
          "=r"((r)[24]), "=r"((r)[25]), "=r"((r)[26]), "=r"((r)[27]), \
          "=r"((r)[28]), "=r"((r)[29]), "=r"((r)[30]), "=r"((r)[31]) \
        : "r"(a))
// SW64 descriptor: layout_type=4, version=1, SBO=32 (512B = 8 rows x 64B), LBO=1
__device__ __forceinline__ uint64_t make_desc64(uint32_t addr) {
    const uint64_t base = (uint64_t(4) << 61) | (uint64_t(1) << 46) |
                          (uint64_t(32) << 32) | (uint64_t(1) << 16);
    return base | ((uint64_t)(addr >> 4) & 0x3FFF);
}
__device__ __forceinline__ void bulk_g2s(uint32_t dst, const void* src, uint32_t bytes, uint32_t mbar) {
    asm volatile("cp.async.bulk.shared::cluster.global.mbarrier::complete_tx::bytes [%0], [%1], %2, [%3];"
                 :: "r"(dst), "l"(src), "r"(bytes), "r"(mbar) : "memory");
}
__device__ __forceinline__ void mbar_expect_tx(uint32_t a, uint32_t bytes) {
    asm volatile("mbarrier.arrive.expect_tx.shared.b64 _, [%0], %1;" :: "r"(a), "r"(bytes) : "memory");
}
#endif  // HAS_TCGEN05

__device__ __forceinline__ void mbar_init(uint32_t a, uint32_t cnt) {
    asm volatile("mbarrier.init.shared.b64 [%0], %1;" :: "r"(a), "r"(cnt) : "memory");
}
__device__ __forceinline__ void mbar_inval(uint32_t a) {
    asm volatile("mbarrier.inval.shared.b64 [%0];" :: "r"(a) : "memory");
}
__device__ __forceinline__ void mbar_arrive(uint32_t a) {
    asm volatile("mbarrier.arrive.shared.b64 _, [%0];" :: "r"(a) : "memory");
}
__device__ __forceinline__ void mbar_wait(uint32_t a, uint32_t parity) {
    uint32_t done;
    asm volatile("{\n\t.reg .pred p;\n\t"
                 "mbarrier.try_wait.parity.acquire.cta.shared::cta.b64 p, [%1], %2;\n\t"
                 "selp.b32 %0, 1, 0, p;\n\t}"
                 : "=r"(done) : "r"(a), "r"(parity) : "memory");
    if (!done) {
        asm volatile("{\n\t.reg .pred P1;\n\t"
                     "WL_%=:\n\t"
                     "mbarrier.try_wait.parity.acquire.cta.shared::cta.b64 P1, [%0], %1, 0x989680;\n\t"
                     "@P1 bra.uni WD_%=;\n\t"
                     "bra.uni WL_%=;\n\t"
                     "WD_%=:\n\t}"
                     :: "r"(a), "r"(parity) : "memory");
    }
}

// ---------------------------------------------------------------------------
// Fallback (mma.sync) helpers — legal on plain compute_103
// ---------------------------------------------------------------------------
__device__ __forceinline__ void ldsm_x4(uint32_t& r0, uint32_t& r1, uint32_t& r2, uint32_t& r3,
                                        uint32_t addr) {
    asm volatile("ldmatrix.sync.aligned.m8n8.x4.shared.b16 {%0,%1,%2,%3}, [%4];"
                 : "=r"(r0), "=r"(r1), "=r"(r2), "=r"(r3) : "r"(addr));
}
__device__ __forceinline__ void mma16816(float* d, const uint32_t* a, uint32_t b0, uint32_t b1) {
    asm volatile("mma.sync.aligned.m16n8k16.row.col.f32.bf16.bf16.f32 "
                 "{%0,%1,%2,%3}, {%4,%5,%6,%7}, {%8,%9}, {%0,%1,%2,%3};"
                 : "+f"(d[0]), "+f"(d[1]), "+f"(d[2]), "+f"(d[3])
                 : "r"(a[0]), "r"(a[1]), "r"(a[2]), "r"(a[3]), "r"(b0), "r"(b1));
}

// ---------------------------------------------------------------------------
// Kernel 1 (merged prep): blocks [0,8192) = A convert (paired uint4 .cs
// stores); [8192,8320) = W1 convert; [8320,8352) = pq.
// ---------------------------------------------------------------------------
__global__ void __launch_bounds__(256)
prep_kernel(const float* __restrict__ values, const float* __restrict__ W1,
            const float* __restrict__ query, const float* __restrict__ W2,
            const float* __restrict__ b1, const float* __restrict__ b2) {
    const int blk = blockIdx.x;
    const int tid = threadIdx.x;
    __shared__ float q[D];

    if (blk < 8192) {
#if HAS_TCGEN05
        const int kc  = blk & 31;
        const int rbp = blk >> 5;            // 0..255 (256-row groups)
        const float4* src = reinterpret_cast<const float4*>(values)
                            + (size_t)rbp*256*256 + kc*8;
        // pair s-octets: pidx 0..1023 -> r (0..255), sp (0..3); s = 2sp, 2sp+1.
        // bit 3 of the byte offset is outside the SW64 XOR mask, so the two
        // uint2 slots stay adjacent & 16B-aligned -> one uint4 store each.
        #pragma unroll
        for (int i = 0; i < 4; i++) {
            int pidx = tid + 256*i;          // 0..1023
            int r  = pidx >> 2;              // 0..255
            int sp = pidx & 3;
            float4 v0 = src[(size_t)r*256 + 2*sp];
            float4 v1 = src[(size_t)r*256 + 2*sp + 1];
            float f0[4] = {v0.x, v0.y, v0.z, v0.w};
            float f1[4] = {v1.x, v1.y, v1.z, v1.w};
            uint2 hp0, lp0, hp1, lp1;
            split4(f0, hp0, lp0);
            split4(f1, hp1, lp1);
            int rbg = rbp*2 + (r >> 7);      // rowblock of 128
            size_t gb = ((size_t)rbg*32 + kc) * 8192;
            uint32_t off = sw64((uint32_t)(r & 127)*64 + (2*sp)*8);
            uint4 hq = make_uint4(hp0.x, hp0.y, hp1.x, hp1.y);
            uint4 lq = make_uint4(lp0.x, lp0.y, lp1.x, lp1.y);
            __stcs((uint4*)((char*)g_Ahi + gb + off), hq);
            __stcs((uint4*)((char*)g_Alo + gb + off), lq);
        }
#endif
    } else if (blk < 8320) {
        const int g2 = blk - 8192;           // 0..127 = pass*32 + kc
#if HAS_TCGEN05
        const int pass = g2 >> 5;
        const int kc = g2 & 31;
        char* dhi = (char*)g_Bhi + (size_t)g2 * 16384;
        char* dlo = (char*)g_Blo + (size_t)g2 * 16384;
        const int k0 = kc*KCH, u0 = pass*256;
        const int ul = tid;
        for (int k4 = 0; k4 < 8; k4++) {
            float f[4];
            #pragma unroll
            for (int j = 0; j < 4; j++) f[j] = W1[(size_t)(k0 + k4*4 + j)*U + u0 + ul];
            uint2 hp, lp;
            split4(f, hp, lp);
            uint32_t off = sw64((uint32_t)ul*64 + k4*8);
            *(uint2*)(dhi + off) = hp;
            *(uint2*)(dlo + off) = lp;
        }
#else
        const int k0 = (g2 & 31)*32;
        const int u  = (g2 >> 5)*256 + tid;
        for (int k4 = 0; k4 < 8; k4++) {
            float f[4];
            #pragma unroll
            for (int j = 0; j < 4; j++) f[j] = W1[(size_t)(k0 + k4*4 + j)*U + u];
            uint2 hp, lp;
            split4(f, hp, lp);
            *(uint2*)&g_Bhi[(size_t)u*WPAD + k0 + k4*4] = hp;
            *(uint2*)&g_Blo[(size_t)u*WPAD + k0 + k4*4] = lp;
        }
#endif
    } else {
        const int b = blk - 8320;
        for (int i = tid; i < D; i += 256) q[i] = query[b*D + i];
        __syncthreads();
        int u = tid;
        float a0 = 0.f, a1 = 0.f, a2 = 0.f, a3 = 0.f;
        for (int d = 0; d < D; d++) {
            float qd = q[d];
            const float* w = &W2[(size_t)d*U + u];
            a0 += qd * w[0];   a1 += qd * w[256];
            a2 += qd * w[512]; a3 += qd * w[768];
        }
        g_pq[b*U + u      ] = a0 + b1[u      ] + b2[u      ];
        g_pq[b*U + u + 256] = a1 + b1[u + 256] + b2[u + 256];
        g_pq[b*U + u + 512] = a2 + b1[u + 512] + b2[u + 512];
        g_pq[b*U + u + 768] = a3 + b1[u + 768] + b2[u + 768];
    }
}

// ---------------------------------------------------------------------------
// Kernel 2a: tcgen05 score GEMM — EXACT r7 (proven 586us).
// ---------------------------------------------------------------------------
#if HAS_TCGEN05
__device__ __forceinline__ void issue_copies(uint32_t sb, int rb, int g) {
    const int slot = g & 3;
    const uint32_t st = sb + OF_STG + slot*STG_BYTES;
    const uint32_t full = sb + OF_FULL + 8*slot;
    mbar_expect_tx(full, STG_TX);
    size_t aoff = ((size_t)rb*32 + (g & 31)) * 8192;
    size_t boff = (size_t)g * 16384;
    bulk_g2s(st + SOF_AHI, (const char*)g_Ahi + aoff,  8192, full);
    bulk_g2s(st + SOF_ALO, (const char*)g_Alo + aoff,  8192, full);
    bulk_g2s(st + SOF_BHI, (const char*)g_Bhi + boff, 16384, full);
    bulk_g2s(st + SOF_BLO, (const char*)g_Blo + boff, 16384, full);
}
#endif

__global__ void __launch_bounds__(NTHREADS, 1)
score_gemm_tc(const float* __restrict__ values, const float* __restrict__ Vv) {
#if HAS_TCGEN05
    const uint32_t raw = smem_u32(dynsmem);
    const uint32_t sb = (raw + 1023) & ~1023u;
    char* sbp = dynsmem + (sb - raw);

    const int tid = threadIdx.x;
    const int wid = tid >> 5;
    const int lane = tid & 31;
    const int rb  = blockIdx.x;
    const int row0 = rb * GM;
    const int bidx = row0 / T;

    if (wid == 0) {
        tm_alloc(sb + OF_TM, 512);
        tm_relinquish();
    }
    if (tid == 0) {
        #pragma unroll
        for (int s = 0; s < 4; s++) {
            mbar_init(sb + OF_FULL + 8*s, 1);
            mbar_init(sb + OF_DONE + 8*s, 1);
        }
        mbar_init(sb + OF_PDONE,     1);
        mbar_init(sb + OF_PDONE + 8, 1);
        mbar_init(sb + OF_EPI,     128);
        mbar_init(sb + OF_EPI + 8, 128);
    }
    {
        ((float4*)(sbp + OF_PQ))[tid] = ((const float4*)(g_pq + bidx*U))[tid];
        ((float4*)(sbp + OF_VV))[tid] = ((const float4*)Vv)[tid];
    }
    __syncthreads();
    const uint32_t tmem = *(volatile uint32_t*)(sbp + OF_TM);

    if (tid == 0) {
        tc_fence_after();
        issue_copies(sb, rb, 0);
        issue_copies(sb, rb, 1);
        issue_copies(sb, rb, 2);
        issue_copies(sb, rb, 3);
        for (int p = 0; p < NPASS; p++) {
            if (p >= 2) {
                mbar_wait(sb + OF_EPI + 8*(p & 1), 0);
                tc_fence_after();
            }
            const uint32_t dt = tmem + (p & 1)*256;
            for (int c = 0; c < NKC; c++) {
                const int g = p*NKC + c;
                const int slot = g & 3;
                mbar_wait(sb + OF_FULL + 8*slot, (uint32_t)((g >> 2) & 1));
                const uint32_t st = sb + OF_STG + slot*STG_BYTES;
                uint64_t adh = make_desc64(st + SOF_AHI);
                uint64_t adl = make_desc64(st + SOF_ALO);
                uint64_t bdh = make_desc64(st + SOF_BHI);
                uint64_t bdl = make_desc64(st + SOF_BLO);
                #pragma unroll
                for (int ks = 0; ks < 2; ks++) {
                    uint64_t o = (uint64_t)(ks*2);
                    uint32_t en0 = (c > 0 || ks > 0) ? 1u : 0u;
                    mma_f16_ss(dt, adh + o, bdh + o, MMA_IDESC, en0);
                    mma_f16_ss(dt, adh + o, bdl + o, MMA_IDESC, 1u);
                    mma_f16_ss(dt, adl + o, bdh + o, MMA_IDESC, 1u);
                }
                tm_commit(sb + OF_DONE + 8*slot);
                if (g >= 1 && g + 3 < NCH) {
                    const int gp = g - 1;
                    mbar_wait(sb + OF_DONE + 8*(gp & 3), (uint32_t)((gp >> 2) & 1));
                    issue_copies(sb, rb, g + 3);
                }
            }
            tm_commit(sb + OF_PDONE + 8*(p & 1));
        }
    } else if (wid >= 4) {
        float score = 0.f;
        const int myrow = (wid - 4)*32 + lane;
        const float* pqs = (const float*)(sbp + OF_PQ);
        const float* vvs = (const float*)(sbp + OF_VV);
        for (int p = 0; p < NPASS; p++) {
            mbar_wait(sb + OF_PDONE + 8*(p & 1), (uint32_t)((p >> 1) & 1));
            tc_fence_after();
            const uint32_t dbase = tmem + (p & 1)*256;
            #pragma unroll
            for (int j = 0; j < 8; j++) {
                uint32_t r[32];
                TCLD32(r, dbase + j*32);
                tc_wait_ld();
                #pragma unroll
                for (int c2 = 0; c2 < 32; c2++) {
                    int u = p*256 + j*32 + c2;
                    float dv = __uint_as_float(r[c2]);
                    score += fast_tanh(dv + pqs[u]) * vvs[u];
                }
            }
            tc_fence_before();
            mbar_arrive(sb + OF_EPI + 8*(p & 1));
        }
        g_score[row0 + myrow] = score;
    }
    __syncthreads();
    if (tid == 0) {
        #pragma unroll
        for (int s = 0; s < 4; s++) {
            mbar_inval(sb + OF_FULL + 8*s);
            mbar_inval(sb + OF_DONE + 8*s);
        }
        mbar_inval(sb + OF_PDONE); mbar_inval(sb + OF_PDONE + 8);
        mbar_inval(sb + OF_EPI);   mbar_inval(sb + OF_EPI + 8);
    }
    __syncthreads();
    if (wid == 0) tm_dealloc(tmem, 512);
#endif  // HAS_TCGEN05
}

// ---------------------------------------------------------------------------
// Kernel 2b: fallback mma.sync (HMMA) score GEMM (body only on plain sm_103)
// ---------------------------------------------------------------------------
__global__ void __launch_bounds__(256)
score_gemm_mma(const float* __restrict__ values, const float* __restrict__ Vv) {
#if !HAS_TCGEN05
    const int tid  = threadIdx.x;
    const int wid  = tid >> 5;
    const int lane = tid & 31;
    const int row0 = blockIdx.x * 128;
    const int bidx = row0 / T;
    const int c = lane & 3;
    const int g = lane >> 2;

    __nv_bfloat16* As_hi = (__nv_bfloat16*)dynsmem;
    __nv_bfloat16* As_lo = As_hi + FB_TILE;
    __nv_bfloat16* Bs_hi = As_lo + FB_TILE;
    __nv_bfloat16* Bs_lo = Bs_hi + FB_TILE;
    const uint32_t smb   = smem_u32(dynsmem);
    const uint32_t ahi_b = smb;
    const uint32_t alo_b = smb + FB_TILE*2;
    const uint32_t bhi_b = smb + 2*FB_TILE*2;
    const uint32_t blo_b = smb + 3*FB_TILE*2;

    float score0 = 0.f, score1 = 0.f;

    for (int p = 0; p < FB_NP; p++) {
        const int u0 = p * 128;
        float acc[16][4];
        #pragma unroll
        for (int i = 0; i < 16; i++)
            #pragma unroll
            for (int j = 0; j < 4; j++) acc[i][j] = 0.f;

        for (int kc = 0; kc < FB_KC; kc++) {
            const int k0 = kc * 64;
            #pragma unroll
            for (int i = 0; i < 8; i++) {
                int idx = tid + 256*i;
                int r = idx >> 4;
                int s = idx & 15;
                float4 v = *(const float4*)&values[(size_t)(row0 + r)*D + k0 + s*4];
                float f[4] = {v.x, v.y, v.z, v.w};
                uint2 hp, lp;
                split4(f, hp, lp);
                *(uint2*)&As_hi[r*FB_STRIDE + s*4] = hp;
                *(uint2*)&As_lo[r*FB_STRIDE + s*4] = lp;
            }
            #pragma unroll
            for (int i = 0; i < 4; i++) {
                int idx = tid + 256*i;
                int n = idx >> 3;
                int m = idx & 7;
                *(uint4*)&Bs_hi[n*FB_STRIDE + m*8] =
                    *(const uint4*)&g_Bhi[(size_t)(u0 + n)*WPAD + k0 + m*8];
                *(uint4*)&Bs_lo[n*FB_STRIDE + m*8] =
                    *(const uint4*)&g_Blo[(size_t)(u0 + n)*WPAD + k0 + m*8];
            }
            __syncthreads();

            #pragma unroll
            for (int ks = 0; ks < 4; ks++) {
                uint32_t ah[4], al[4];
                uint32_t aoff = ((uint32_t)(16*wid + (lane & 15))*FB_STRIDE
                                 + ks*16 + ((lane >> 4) << 3)) * 2;
                ldsm_x4(ah[0], ah[1], ah[2], ah[3], ahi_b + aoff);
                ldsm_x4(al[0], al[1], al[2], al[3], alo_b + aoff);

                #pragma unroll
                for (int nt2 = 0; nt2 < 8; nt2++) {
                    int mtx = lane >> 3, r8 = lane & 7;
                    uint32_t n   = nt2*16 + ((mtx >> 1) << 3) + r8;
                    uint32_t kof = ks*16 + ((mtx & 1) << 3);
                    uint32_t boff = (n*FB_STRIDE + kof) * 2;
                    uint32_t bh0, bh1, bh2, bh3, bl0, bl1, bl2, bl3;
                    ldsm_x4(bh0, bh1, bh2, bh3, bhi_b + boff);
                    ldsm_x4(bl0, bl1, bl2, bl3, blo_b + boff);
                    mma16816(acc[2*nt2],     ah, bh0, bh1);
                    mma16816(acc[2*nt2],     ah, bl0, bl1);
                    mma16816(acc[2*nt2],     al, bh0, bh1);
                    mma16816(acc[2*nt2 + 1], ah, bh2, bh3);
                    mma16816(acc[2*nt2 + 1], ah, bl2, bl3);
                    mma16816(acc[2*nt2 + 1], al, bh2, bh3);
                }
            }
            __syncthreads();
        }

        #pragma unroll
        for (int nt = 0; nt < 16; nt++) {
            #pragma unroll
            for (int j = 0; j < 2; j++) {
                int u = u0 + nt*8 + 2*c + j;
                float pqv = g_pq[bidx*U + u];
                float vv  = Vv[u];
                score0 += tanhf(acc[nt][j]     + pqv) * vv;
                score1 += tanhf(acc[nt][2 + j] + pqv) * vv;
            }
        }
    }

    score0 += __shfl_xor_sync(0xffffffffu, score0, 1);
    score0 += __shfl_xor_sync(0xffffffffu, score0, 2);
    score1 += __shfl_xor_sync(0xffffffffu, score1, 1);
    score1 += __shfl_xor_sync(0xffffffffu, score1, 2);
    if (c == 0) {
        g_score[row0 + wid*16 + g]     = score0;
        g_score[row0 + wid*16 + 8 + g] = score1;
    }
#endif  // !HAS_TCGEN05
}

// ---------------------------------------------------------------------------
// Kernel 3: mask + softmax over T -> attention weights (r7-proven)
// ---------------------------------------------------------------------------
__global__ void softmax_kernel(const float* __restrict__ mask,
                               const float* __restrict__ bV,
                               float* __restrict__ attn) {
    const int b = blockIdx.x;
    __shared__ float sc[T];
    __shared__ float redbuf[256];
    const float bv = bV[0];

    for (int t = threadIdx.x; t < T; t += 256)
        sc[t] = g_score[b*T + t] + bv + mask[b*T + t] * (-1e9f);
    __syncthreads();

    float m = -INFINITY;
    for (int t = threadIdx.x; t < T; t += 256) m = fmaxf(m, sc[t]);
    redbuf[threadIdx.x] = m;
    __syncthreads();
    for (int s = 128; s > 0; s >>= 1) {
        if (threadIdx.x < s) redbuf[threadIdx.x] = fmaxf(redbuf[threadIdx.x], redbuf[threadIdx.x + s]);
        __syncthreads();
    }
    m = redbuf[0];
    __syncthreads();

    float sum = 0.f;
    for (int t = threadIdx.x; t < T; t += 256) {
        float e = expf(sc[t] - m);
        sc[t] = e;
        sum += e;
    }
    redbuf[threadIdx.x] = sum;
    __syncthreads();
    for (int s = 128; s > 0; s >>= 1) {
        if (threadIdx.x < s) redbuf[threadIdx.x] += redbuf[threadIdx.x + s];
        __syncthreads();
    }
    const float inv = 1.f / redbuf[0];
    __syncthreads();

    for (int t = threadIdx.x; t < T; t += 256) attn[b*T + t] = sc[t] * inv;
}

// ---------------------------------------------------------------------------
// Kernel 4/5: context = sum_t attn * values (r7-proven, TS=16)
// ---------------------------------------------------------------------------
__global__ void __launch_bounds__(256)
context_partial_kernel(const float* __restrict__ values,
                       const float* __restrict__ attn) {
    const int ts = blockIdx.x;
    const int b  = blockIdx.y;
    const int t0 = ts * (T / TS);
    const int tid = threadIdx.x;

    __shared__ float w[T / TS];
    if (tid < T / TS) w[tid] = attn[b*T + t0 + tid];
    __syncthreads();

    const float4* vp = (const float4*)(values + ((size_t)b*T + t0) * D) + tid;
    float4 acc = make_float4(0.f, 0.f, 0.f, 0.f);
    #pragma unroll 4
    for (int t = 0; t < T / TS; t++) {
        float4 v = vp[(size_t)t * (D/4)];
        float wt = w[t];
        acc.x += wt * v.x; acc.y += wt * v.y;
        acc.z += wt * v.z; acc.w += wt * v.w;
    }
    ((float4*)(g_ctxp + ((size_t)ts*B + b) * D))[tid] = acc;
}

__global__ void context_reduce_kernel(float* __restrict__ ctx) {
    int i = blockIdx.x * 256 + threadIdx.x;
    float s = 0.f;
    #pragma unroll
    for (int p = 0; p < TS; p++) s += g_ctxp[(size_t)p*B*D + i];
    ctx[i] = s;
}

// ---------------------------------------------------------------------------
extern "C" void kernel_launch(void* const* d_in, const int* in_sizes, int n_in,
                              void* d_out, int out_size) {
    const float* values = (const float*)d_in[0];
    const float* query  = (const float*)d_in[1];
    const float* mask   = (const float*)d_in[2];
    const float* W1     = (const float*)d_in[3];
    const float* b1     = (const float*)d_in[4];
    const float* W2     = (const float*)d_in[5];
    const float* b2     = (const float*)d_in[6];
    const float* Vv     = (const float*)d_in[7];
    const float* bV     = (const float*)d_in[8];

    float* ctx  = (float*)d_out;
    float* attn = (float*)d_out + B*D;

    cudaFuncSetAttribute(score_gemm_tc,  cudaFuncAttributeMaxDynamicSharedMemorySize, SMEM_BYTES);
    cudaFuncSetAttribute(score_gemm_mma, cudaFuncAttributeMaxDynamicSharedMemorySize, FB_SMEM);

    // Runtime arch dispatch: cc>=10 -> tcgen05 cubin exists and is the
    // executed path (proven r3-r14); skip the dead fallback launch entirely.
    // (Host attribute query is deterministic and executes at capture time
    // only — replays see a graph with one fewer node.)
    int dev = 0, cc_major = 0;
    cudaGetDevice(&dev);
    cudaDeviceGetAttribute(&cc_major, cudaDevAttrComputeCapabilityMajor, dev);

    prep_kernel<<<8352, 256>>>(values, W1, query, W2, b1, b2);

    if (cc_major >= 10) {
        score_gemm_tc <<<NROWS/GM, NTHREADS, SMEM_BYTES>>>(values, Vv);
    } else {
        score_gemm_mma<<<NROWS/128, 256, FB_SMEM>>>(values, Vv);
    }

    softmax_kernel<<<B, 256>>>(mask, bV, attn);
    dim3 cgrid(TS, B);
    context_partial_kernel<<<cgrid, 256>>>(values, attn);
    context_reduce_kernel<<<(B*D)/256, 256>>>(ctx);
}